// round 2
// baseline (speedup 1.0000x reference)
#include <cuda_runtime.h>
#include <cstdint>

// ---------------------------------------------------------------------------
// RipsECC: Euler characteristic curve of the Rips 1-skeleton.
//   B=4096 points in [0,1]^3, 64 bins, bin(d) = ceil(31.5*d) in [0,55].
//   All 8,386,560 i<j pairs are edges (max d = sqrt(3) < t_max = 2).
//   out = cumsum over bins of (+4096 at bin 0) - edge_histogram.
// Single fused kernel: per-warp lane-private smem histograms (conflict-free),
// per-block partials to global, last block reduces + scans (threadfence
// reduction pattern; ticket self-resets so the launch is graph-replayable).
// ---------------------------------------------------------------------------

#define NPTS      4096
#define NSTEPS    64
#define NTHREADS  512
#define NWARPS    16                       // warps per block
#define NBLOCKS   (NPTS / 2 / NWARPS)      // 128: warp-unit u owns rows {u, 4095-u}
#define PAD       4128                     // 4096 + 32 tail padding
#define HIST_WORDS (NWARPS * NSTEPS * 32)  // 32768 words = 128 KB
#define SMEM_FLOATS (3 * PAD + HIST_WORDS)
#define SMEM_BYTES  (SMEM_FLOATS * 4)      // 180608 B

__device__ int      g_part[NBLOCKS][NSTEPS];
__device__ unsigned g_ticket = 0;

// One pair. Approximate sqrt: ceil(31.5*sqrt(d2)) = ceil(sqrt(992.25*d2)),
// computed as m*rsqrt(m) (MUFU + 2 FMUL). d2==0 -> 0*inf = NaN -> F2I -> 0,
// which matches ceil(0)=0. Misbinning is only possible within ~2e-7 relative
// of a bin boundary: O(100) edges of 8.39M, far under the 1e-3 tolerance.
__device__ __forceinline__ void pair_body(float xi, float yi, float zi,
                                          const float* __restrict__ xs,
                                          const float* __restrict__ ys,
                                          const float* __restrict__ zs,
                                          unsigned* myhist, int j) {
    float dx = xi - xs[j];
    float dy = yi - ys[j];
    float dz = zi - zs[j];
    float d2 = fmaf(dx, dx, fmaf(dy, dy, dz * dz));
    float m  = d2 * 992.25f;              // (31.5)^2
    float r  = __frsqrt_rn(m);            // MUFU.RSQ
    int   t  = __float2int_ru(m * r);     // ceil(sqrt(m)), t in [0,55]
    // lane-owned slot: word = t*32 + lane -> bank == lane, conflict-free
    myhist[t << 5] += 1u;
}

__device__ __forceinline__ void process_row(int i, int lane,
                                            const float* __restrict__ xs,
                                            const float* __restrict__ ys,
                                            const float* __restrict__ zs,
                                            unsigned* myhist) {
    if (i >= NPTS - 1) return;
    float xi = xs[i], yi = ys[i], zi = zs[i];
    int cnt   = NPTS - 1 - i;          // j = i+1 .. 4095
    int kfull = cnt >> 5;              // full-warp iterations
    int j = i + 1 + lane;
    int k = 0;
    for (; k + 4 <= kfull; k += 4) {
        pair_body(xi, yi, zi, xs, ys, zs, myhist, j);
        pair_body(xi, yi, zi, xs, ys, zs, myhist, j + 32);
        pair_body(xi, yi, zi, xs, ys, zs, myhist, j + 64);
        pair_body(xi, yi, zi, xs, ys, zs, myhist, j + 96);
        j += 128;
    }
    for (; k < kfull; k++) {
        pair_body(xi, yi, zi, xs, ys, zs, myhist, j);
        j += 32;
    }
    if (j < NPTS)   // tail (pad reads are zero-filled; update guarded)
        pair_body(xi, yi, zi, xs, ys, zs, myhist, j);
}

extern __shared__ float smem_f[];

__global__ void __launch_bounds__(NTHREADS, 1)
rips_ecc_kernel(const float* __restrict__ x, float* __restrict__ out) {
    float* xs = smem_f;
    float* ys = smem_f + PAD;
    float* zs = smem_f + 2 * PAD;
    unsigned* hist = (unsigned*)(smem_f + 3 * PAD);  // [NWARPS][NSTEPS][32]

    const int tid = threadIdx.x;

    // Stage all 4096 points into shared (SoA), zero the 32-element pad.
    for (int idx = tid; idx < PAD; idx += NTHREADS) {
        float a = 0.f, b = 0.f, c = 0.f;
        if (idx < NPTS) {
            a = x[3 * idx + 0];
            b = x[3 * idx + 1];
            c = x[3 * idx + 2];
        }
        xs[idx] = a; ys[idx] = b; zs[idx] = c;
    }
    // Zero the per-warp histograms (128 KB) with 16B stores.
    uint4* h4 = (uint4*)hist;
    for (int idx = tid; idx < HIST_WORDS / 4; idx += NTHREADS)
        h4[idx] = make_uint4(0u, 0u, 0u, 0u);
    __syncthreads();

    const int warp = tid >> 5;
    const int lane = tid & 31;
    unsigned* myhist = hist + warp * (NSTEPS * 32) + lane;

    // Balanced triangular decomposition: warp-unit u owns rows u and 4095-u,
    // exactly 4095 pairs per warp.
    const int u = blockIdx.x * NWARPS + warp;
    process_row(u,            lane, xs, ys, zs, myhist);
    process_row(NPTS - 1 - u, lane, xs, ys, zs, myhist);

    __syncthreads();

    // Block reduction: warp w reduces bins [4w, 4w+4) across the 16 warp hists.
    #pragma unroll
    for (int bb = 0; bb < 4; bb++) {
        int b = warp * 4 + bb;
        unsigned s = 0;
        #pragma unroll
        for (int wi = 0; wi < NWARPS; wi++)
            s += hist[wi * (NSTEPS * 32) + (b << 5) + lane];
        #pragma unroll
        for (int o = 16; o > 0; o >>= 1)
            s += __shfl_down_sync(0xffffffffu, s, o);
        if (lane == 0) {
            g_part[blockIdx.x][b] = (int)s;
            __threadfence();   // writer-side release before the ticket
        }
    }
    __syncthreads();

    // Threadfence-reduction handoff: last block to arrive finalizes.
    __shared__ int s_last;
    if (tid == 0) {
        unsigned t = atomicAdd(&g_ticket, 1u);
        s_last = (t == NBLOCKS - 1);
    }
    __syncthreads();
    if (!s_last) return;
    __threadfence();           // acquire side

    // --- last block: reduce 128x64 partials, cumsum, write out, reset ---
    int* red = (int*)smem_f;           // [64][8]
    {
        int bin = tid & 63;
        int grp = tid >> 6;            // 0..7
        int s = 0;
        #pragma unroll
        for (int b = grp; b < NBLOCKS; b += 8)
            s += g_part[b][bin];
        red[bin * 8 + grp] = s;
    }
    __syncthreads();
    int* ecc = (int*)(smem_f + 1024);  // [64]
    if (tid < NSTEPS) {
        int tot = 0;
        #pragma unroll
        for (int g = 0; g < 8; g++) tot += red[tid * 8 + g];
        ecc[tid] = (tid == 0 ? NPTS : 0) - tot;
    }
    __syncthreads();
    if (tid < 32) {
        int e0 = ecc[tid];
        int e1 = ecc[tid + 32];
        #pragma unroll
        for (int d = 1; d < 32; d <<= 1) {
            int t = __shfl_up_sync(0xffffffffu, e0, d);
            if (tid >= d) e0 += t;
        }
        int tot = __shfl_sync(0xffffffffu, e0, 31);
        #pragma unroll
        for (int d = 1; d < 32; d <<= 1) {
            int t = __shfl_up_sync(0xffffffffu, e1, d);
            if (tid >= d) e1 += t;
        }
        e1 += tot;
        out[tid]      = (float)e0;
        out[tid + 32] = (float)e1;
    }
    if (tid == 0) g_ticket = 0;        // self-reset for graph replay
}

extern "C" void kernel_launch(void* const* d_in, const int* in_sizes, int n_in,
                              void* d_out, int out_size) {
    (void)in_sizes; (void)n_in; (void)out_size;
    const float* x = (const float*)d_in[0];
    float* out = (float*)d_out;

    cudaFuncSetAttribute(rips_ecc_kernel,
                         cudaFuncAttributeMaxDynamicSharedMemorySize, SMEM_BYTES);

    rips_ecc_kernel<<<NBLOCKS, NTHREADS, SMEM_BYTES>>>(x, out);
}

// round 3
// speedup vs baseline: 1.0024x; 1.0024x over previous
#include <cuda_runtime.h>
#include <cstdint>

// ---------------------------------------------------------------------------
// RipsECC. B=4096 points in [0,1]^3, 64 bins, bin(d) = ceil(31.5*d) in [0,55].
// All C(4096,2)=8,386,560 pairs are edges. out = cumsum(+4096 at bin0 - hist).
//
// Decomposition: 128 i-blocks of 32 rows. Lane owns point i = 32*b + lane.
// Units (2208 total): per block b, 1 diagonal tile + ceil((127-b)/4) chunks of
// 128 j's. unit = warp*148 + blockIdx -> every SM busy, <=1 unit per warp.
// Per j: ONE broadcast LDS.128; m = (31.5 d)^2 via norm trick (4 FFMA/FADD);
// bin = F2I.RU(sqrt.approx(m)); lane-private conflict-free smem histogram.
// ---------------------------------------------------------------------------

#define NPTS      4096
#define NSTEPS    64
#define NTHREADS  512
#define NWARPS    16
#define NBLOCKS   148
#define NUNITS    2208                      // 128 diag + 2080 full chunks
#define HIST_WORDS (NWARPS * NSTEPS * 32)   // 32768 words = 128 KB
#define SMEM_BYTES (NPTS * 16 + HIST_WORDS * 4)   // 64KB + 128KB = 196608 B

__device__ int      g_part[NBLOCKS][NSTEPS];
__device__ unsigned g_ticket = 0;

// bin = ceil(31.5*d) = ceil(sqrt(m)), m = 992.25*d2 via norm expansion.
__device__ __forceinline__ int bin_of(float A, float B, float C, float K,
                                      float4 p) {
    float acc = K + p.w;
    float m = fmaf(A, p.x, fmaf(B, p.y, fmaf(C, p.z, acc)));
    float d;
    asm("sqrt.approx.f32 %0, %1;" : "=f"(d) : "f"(m));  // MUFU.SQRT
    return __float2int_ru(d);                           // t in [0, 55]
}

extern __shared__ float4 smem4[];

__global__ void __launch_bounds__(NTHREADS, 1)
rips_ecc_kernel(const float* __restrict__ x, float* __restrict__ out) {
    float4*   pts  = smem4;                         // [4096] (x,y,z,992.25*|p|^2)
    unsigned* hist = (unsigned*)(smem4 + NPTS);     // [16][64][32]

    const int tid = threadIdx.x;

    // Stage points (SoA->AoS float4 with scaled squared norm).
    for (int i = tid; i < NPTS; i += NTHREADS) {
        float a = x[3 * i + 0];
        float b = x[3 * i + 1];
        float c = x[3 * i + 2];
        float n = 992.25f * fmaf(a, a, fmaf(b, b, c * c));
        pts[i] = make_float4(a, b, c, n);
    }
    // Zero 128KB of per-warp histograms with 16B stores.
    uint4* h4 = (uint4*)hist;
    for (int i = tid; i < HIST_WORDS / 4; i += NTHREADS)
        h4[i] = make_uint4(0u, 0u, 0u, 0u);
    __syncthreads();

    const int warp = tid >> 5;
    const int lane = tid & 31;
    unsigned* myhist = hist + warp * (NSTEPS * 32) + lane;  // bank == lane

    const int u = warp * NBLOCKS + blockIdx.x;
    if (u < NUNITS) {
        // Decode unit -> (i-block b, chunk rem). cnt(b) = 1 + ceil((127-b)/4).
        int b = 0, rem = u;
        while (true) {
            int cnt = 1 + ((130 - b) >> 2);
            if (rem < cnt) break;
            rem -= cnt;
            ++b;
        }
        const int ibase = b << 5;
        float4 pi = pts[ibase + lane];
        const float A = -1984.5f * pi.x;   // -2 * 992.25
        const float B = -1984.5f * pi.y;
        const float C = -1984.5f * pi.z;
        const float K = pi.w;

        if (rem == 0) {
            // Diagonal 32x32 tile: j = ibase+1 .. ibase+31, count only j > i.
            #pragma unroll 4
            for (int jj = 1; jj < 32; jj++) {
                float4 p = pts[ibase + jj];
                int t = bin_of(A, B, C, K, p);
                unsigned inc = (jj > lane) ? 1u : 0u;
                myhist[t << 5] += inc;
            }
        } else {
            // Full chunk: 128 (or tail multiple of 32) j's, broadcast loads.
            int j0 = ibase + 32 + ((rem - 1) << 7);
            int j1 = min(j0 + 128, NPTS);
            #pragma unroll 4
            for (int j = j0; j < j1; j++) {
                float4 p = pts[j];
                int t = bin_of(A, B, C, K, p);
                myhist[t << 5] += 1u;
            }
        }
    }
    __syncthreads();

    // Block reduction: warp w reduces bins [4w, 4w+4) across 16 warp hists.
    #pragma unroll
    for (int bb = 0; bb < 4; bb++) {
        int bin = warp * 4 + bb;
        unsigned s = 0;
        #pragma unroll
        for (int wi = 0; wi < NWARPS; wi++)
            s += hist[wi * (NSTEPS * 32) + (bin << 5) + lane];
        #pragma unroll
        for (int o = 16; o > 0; o >>= 1)
            s += __shfl_down_sync(0xffffffffu, s, o);
        if (lane == 0)
            g_part[blockIdx.x][bin] = (int)s;
    }
    __threadfence();           // release partials before taking the ticket
    __syncthreads();

    __shared__ int s_last;
    if (tid == 0)
        s_last = (atomicAdd(&g_ticket, 1u) == NBLOCKS - 1);
    __syncthreads();
    if (!s_last) return;
    __threadfence();           // acquire side

    // --- last block: reduce 148x64 partials, cumsum, write, reset ticket ---
    __shared__ int red[NSTEPS * 8];
    {
        int bin = tid & 63;
        int grp = tid >> 6;    // 0..7
        int s = 0;
        for (int b2 = grp; b2 < NBLOCKS; b2 += 8)
            s += g_part[b2][bin];
        red[bin * 8 + grp] = s;
    }
    __syncthreads();
    __shared__ int ecc[NSTEPS];
    if (tid < NSTEPS) {
        int tot = 0;
        #pragma unroll
        for (int g = 0; g < 8; g++) tot += red[tid * 8 + g];
        ecc[tid] = (tid == 0 ? NPTS : 0) - tot;
    }
    __syncthreads();
    if (tid < 32) {
        int e0 = ecc[tid];
        int e1 = ecc[tid + 32];
        #pragma unroll
        for (int d = 1; d < 32; d <<= 1) {
            int t = __shfl_up_sync(0xffffffffu, e0, d);
            if (tid >= d) e0 += t;
        }
        int tot = __shfl_sync(0xffffffffu, e0, 31);
        #pragma unroll
        for (int d = 1; d < 32; d <<= 1) {
            int t = __shfl_up_sync(0xffffffffu, e1, d);
            if (tid >= d) e1 += t;
        }
        e1 += tot;
        out[tid]      = (float)e0;
        out[tid + 32] = (float)e1;
    }
    if (tid == 0) g_ticket = 0;   // self-reset for graph replay
}

extern "C" void kernel_launch(void* const* d_in, const int* in_sizes, int n_in,
                              void* d_out, int out_size) {
    (void)in_sizes; (void)n_in; (void)out_size;
    const float* x = (const float*)d_in[0];
    float* out = (float*)d_out;

    cudaFuncSetAttribute(rips_ecc_kernel,
                         cudaFuncAttributeMaxDynamicSharedMemorySize, SMEM_BYTES);

    rips_ecc_kernel<<<NBLOCKS, NTHREADS, SMEM_BYTES>>>(x, out);
}

// round 4
// speedup vs baseline: 1.6080x; 1.6042x over previous
#include <cuda_runtime.h>
#include <cstdint>

// ---------------------------------------------------------------------------
// RipsECC. B=4096 points in [0,1]^3, 64 bins, bin(d) = ceil(31.5*d) in [0,55].
// All C(4096,2)=8,386,560 pairs are edges. out = cumsum(+4096 at bin0 - hist).
//
// Latency-hiding redesign: 148 blocks x 1024 threads (32 warps/SM).
// Units: per 32-row i-block b: 1 diagonal tile + floor((128-b)/2) chunks of
// 64 j's (4224 units over 4736 warp-slots, <=1 unit/warp, ~64 iters/warp).
// u16 histograms: warp pair shares a 32-bit word (lo/hi halves, byte-enabled
// STS.U16 -> race-free), 16 regions x 64 bins x 32 lanes = 128 KB.
// Inner loop: groups of 8 front-batched broadcast LDS.128 (MLP=8), then
// compute + hist RMW; fully compile-time unrolled.
// ---------------------------------------------------------------------------

#define NPTS      4096
#define NSTEPS    64
#define NTHREADS  1024
#define NWARPS    32
#define NBLOCKS   148
#define NUNITS    4224
#define NREGIONS  16
#define HIST_WORDS (NREGIONS * NSTEPS * 32)        // 32768 words = 128 KB
#define SMEM_BYTES (NPTS * 16 + HIST_WORDS * 4)    // 64KB + 128KB

__device__ int      g_part[NBLOCKS][NSTEPS];
__device__ unsigned g_ticket = 0;

// bin = ceil(31.5*d) = ceil(sqrt(m)); m = 992.25*d2 via norm expansion.
__device__ __forceinline__ int bin_of(float A, float B, float C, float K,
                                      float4 p) {
    float m = fmaf(A, p.x, fmaf(B, p.y, fmaf(C, p.z, K + p.w)));
    float d;
    asm("sqrt.approx.f32 %0, %1;" : "=f"(d) : "f"(m));   // MUFU.SQRT
    return __float2int_ru(d);                            // t in [0, 55]
}

// 32 consecutive j's, all lanes vs their own i. Groups of 8: batch the 8
// broadcast LDS.128 up front (MLP), then compute and hist-RMW.
__device__ __forceinline__ void do32(const float4* __restrict__ pts, int j0,
                                     float A, float B, float C, float K,
                                     unsigned short* __restrict__ myh) {
    #pragma unroll
    for (int g = 0; g < 4; g++) {
        float4 p[8];
        #pragma unroll
        for (int q = 0; q < 8; q++)
            p[q] = pts[j0 + g * 8 + q];
        #pragma unroll
        for (int q = 0; q < 8; q++) {
            int t = bin_of(A, B, C, K, p[q]);
            myh[t << 6] += (unsigned short)1;   // byte addr = t*128, bank=lane
        }
    }
}

extern __shared__ float4 smem4[];

__global__ void __launch_bounds__(NTHREADS, 1)
rips_ecc_kernel(const float* __restrict__ x, float* __restrict__ out) {
    float4*   pts  = smem4;                       // [4096] (x,y,z, 992.25|p|^2)
    unsigned* hist = (unsigned*)(smem4 + NPTS);   // [16 regions][64][32] u32

    const int tid = threadIdx.x;

    for (int i = tid; i < NPTS; i += NTHREADS) {
        float a = x[3 * i + 0];
        float b = x[3 * i + 1];
        float c = x[3 * i + 2];
        pts[i] = make_float4(a, b, c, 992.25f * fmaf(a, a, fmaf(b, b, c * c)));
    }
    uint4* h4 = (uint4*)hist;
    for (int i = tid; i < HIST_WORDS / 4; i += NTHREADS)
        h4[i] = make_uint4(0u, 0u, 0u, 0u);
    __syncthreads();

    const int warp = tid >> 5;
    const int lane = tid & 31;
    // warp pair shares a word: region = warp>>1, halfword = warp&1
    unsigned short* myh = (unsigned short*)((char*)hist +
                          (warp >> 1) * 8192 + lane * 4 + (warp & 1) * 2);

    const int u = warp * NBLOCKS + blockIdx.x;
    if (u < NUNITS) {
        // prefix(b) = b + 4096 - ((128-b)^2 >> 2); invert with sqrt guess.
        float fv = -2.0f + 2.0f * sqrtf((float)(4225 - u));
        int b = 128 - (int)fv;
        b = max(0, min(127, b));
        while (b > 0 && (b + 4096 - (((128 - b) * (128 - b)) >> 2)) > u) --b;
        while (b < 127 &&
               ((b + 1) + 4096 - (((127 - b) * (127 - b)) >> 2)) <= u) ++b;
        const int rem   = u - (b + 4096 - (((128 - b) * (128 - b)) >> 2));
        const int ibase = b << 5;

        float4 pi = pts[ibase + lane];
        const float A = -1984.5f * pi.x;   // -2 * 992.25
        const float B = -1984.5f * pi.y;
        const float C = -1984.5f * pi.z;
        const float K = pi.w;

        if (rem == 0) {
            // Diagonal 32x32 tile: j = ibase+jj, count only jj > lane.
            #pragma unroll
            for (int jj = 1; jj < 32; jj++) {
                float4 p = pts[ibase + jj];
                int t = bin_of(A, B, C, K, p);
                if (jj > lane)
                    myh[t << 6] += (unsigned short)1;
            }
        } else {
            // Chunk of 64 (or trailing 32) j's starting past the diagonal.
            int j0 = ibase + 32 + ((rem - 1) << 6);
            do32(pts, j0, A, B, C, K, myh);
            if (j0 + 32 < NPTS)
                do32(pts, j0 + 32, A, B, C, K, myh);
        }
    }
    __syncthreads();

    // Block reduction: warp w reduces bins {2w, 2w+1} across 16 regions.
    #pragma unroll
    for (int bb = 0; bb < 2; bb++) {
        int bin = warp * 2 + bb;
        unsigned s = 0;
        #pragma unroll
        for (int r = 0; r < NREGIONS; r++)
            s += hist[r * 2048 + (bin << 5) + lane];
        s = (s & 0xFFFFu) + (s >> 16);     // lo+hi halves (no carry: sums<64K)
        #pragma unroll
        for (int o = 16; o > 0; o >>= 1)
            s += __shfl_down_sync(0xffffffffu, s, o);
        if (lane == 0)
            g_part[blockIdx.x][bin] = (int)s;
    }
    __threadfence();
    __syncthreads();

    __shared__ int s_last;
    if (tid == 0)
        s_last = (atomicAdd(&g_ticket, 1u) == NBLOCKS - 1);
    __syncthreads();
    if (!s_last) return;
    __threadfence();

    // --- last block: reduce 148x64 partials, cumsum, write, reset ---
    __shared__ int red[NSTEPS * 16];
    {
        int bin = tid & 63;
        int grp = tid >> 6;               // 0..15
        int s = 0;
        for (int b2 = grp; b2 < NBLOCKS; b2 += 16)
            s += g_part[b2][bin];
        red[bin * 16 + grp] = s;
    }
    __syncthreads();
    __shared__ int ecc[NSTEPS];
    if (tid < NSTEPS) {
        int tot = 0;
        #pragma unroll
        for (int g = 0; g < 16; g++) tot += red[tid * 16 + g];
        ecc[tid] = (tid == 0 ? NPTS : 0) - tot;
    }
    __syncthreads();
    if (tid < 32) {
        int e0 = ecc[tid];
        int e1 = ecc[tid + 32];
        #pragma unroll
        for (int d = 1; d < 32; d <<= 1) {
            int t = __shfl_up_sync(0xffffffffu, e0, d);
            if (tid >= d) e0 += t;
        }
        int tot = __shfl_sync(0xffffffffu, e0, 31);
        #pragma unroll
        for (int d = 1; d < 32; d <<= 1) {
            int t = __shfl_up_sync(0xffffffffu, e1, d);
            if (tid >= d) e1 += t;
        }
        e1 += tot;
        out[tid]      = (float)e0;
        out[tid + 32] = (float)e1;
    }
    if (tid == 0) g_ticket = 0;   // self-reset for graph replay
}

extern "C" void kernel_launch(void* const* d_in, const int* in_sizes, int n_in,
                              void* d_out, int out_size) {
    (void)in_sizes; (void)n_in; (void)out_size;
    const float* x = (const float*)d_in[0];
    float* out = (float*)d_out;

    cudaFuncSetAttribute(rips_ecc_kernel,
                         cudaFuncAttributeMaxDynamicSharedMemorySize, SMEM_BYTES);

    rips_ecc_kernel<<<NBLOCKS, NTHREADS, SMEM_BYTES>>>(x, out);
}

// round 5
// speedup vs baseline: 1.6110x; 1.0019x over previous
#include <cuda_runtime.h>
#include <cstdint>

// ---------------------------------------------------------------------------
// RipsECC. B=4096 points in [0,1]^3, 64 bins, bin(d) = ceil(31.5*d) in [0,55].
// All C(4096,2)=8,386,560 pairs are edges. out = cumsum(+4096 at bin0 - hist).
//
// 148 blocks x 1024 threads. Units: per 32-row i-block b, 1 diagonal tile +
// chunks of 64 j's (4224 units over 4736 warp-slots). Lane owns i=32b+lane.
// Inner loop: TWO independent streams per warp (j0+jj and j0+32+jj) so two
// ~105-cycle dependence chains overlap. u8 histograms, 2 byte-banks per warp
// (one per stream); warp-pair shares a u32 word -> still 128 KB total.
// Final reduce uses dp4a to sum the 4 bytes of each word.
// ---------------------------------------------------------------------------

#define NPTS      4096
#define NSTEPS    64
#define NTHREADS  1024
#define NBLOCKS   148
#define NUNITS    4224
#define NREGIONS  16
#define HIST_WORDS (NREGIONS * NSTEPS * 32)        // 32768 words = 128 KB
#define SMEM_BYTES (NPTS * 16 + HIST_WORDS * 4)    // 64KB + 128KB

__device__ int      g_part[NBLOCKS][NSTEPS];
__device__ unsigned g_ticket = 0;

// bin = ceil(31.5*d) = ceil(sqrt(m)); m = 992.25*d2 via norm expansion.
__device__ __forceinline__ int bin_of(float A, float B, float C, float K,
                                      float4 p) {
    float m = fmaf(A, p.x, fmaf(B, p.y, fmaf(C, p.z, K + p.w)));
    float d;
    asm("sqrt.approx.f32 %0, %1;" : "=f"(d) : "f"(m));   // MUFU.SQRT
    return __float2int_ru(d);                            // t in [0, 55]
}

extern __shared__ float4 smem4[];

__global__ void __launch_bounds__(NTHREADS, 1)
rips_ecc_kernel(const float* __restrict__ x, float* __restrict__ out) {
    float4*   pts  = smem4;                       // [4096] (x,y,z, 992.25|p|^2)
    unsigned* hist = (unsigned*)(smem4 + NPTS);   // [16][64][32] u32 words

    const int tid = threadIdx.x;

    for (int i = tid; i < NPTS; i += NTHREADS) {
        float a = x[3 * i + 0];
        float b = x[3 * i + 1];
        float c = x[3 * i + 2];
        pts[i] = make_float4(a, b, c, 992.25f * fmaf(a, a, fmaf(b, b, c * c)));
    }
    uint4* h4 = (uint4*)hist;
    for (int i = tid; i < HIST_WORDS / 4; i += NTHREADS)
        h4[i] = make_uint4(0u, 0u, 0u, 0u);
    __syncthreads();

    const int warp = tid >> 5;
    const int lane = tid & 31;
    // word layout per (region=warp>>1, bin, lane): bytes =
    //   [warpEven.bank0, warpEven.bank1, warpOdd.bank0, warpOdd.bank1]
    unsigned char* myh0 = (unsigned char*)hist +
                          (warp >> 1) * 8192 + lane * 4 + (warp & 1) * 2;
    unsigned char* myh1 = myh0 + 1;

    const int u = warp * NBLOCKS + blockIdx.x;
    if (u < NUNITS) {
        // prefix(b) = b + 4096 - ((128-b)^2 >> 2); invert with sqrt guess.
        float fv = -2.0f + 2.0f * sqrtf((float)(4225 - u));
        int b = 128 - (int)fv;
        b = max(0, min(127, b));
        while (b > 0 && (b + 4096 - (((128 - b) * (128 - b)) >> 2)) > u) --b;
        while (b < 127 &&
               ((b + 1) + 4096 - (((127 - b) * (127 - b)) >> 2)) <= u) ++b;
        const int rem   = u - (b + 4096 - (((128 - b) * (128 - b)) >> 2));
        const int ibase = b << 5;

        float4 pi = pts[ibase + lane];
        const float A = -1984.5f * pi.x;   // -2 * 992.25
        const float B = -1984.5f * pi.y;
        const float C = -1984.5f * pi.z;
        const float K = pi.w;

        if (rem == 0) {
            // Diagonal 32x32 tile: j = ibase+jj, count only jj > lane.
            #pragma unroll 4
            for (int jj = 1; jj < 32; jj++) {
                float4 p = pts[ibase + jj];
                int t = bin_of(A, B, C, K, p);
                if (jj > lane)
                    myh0[t << 7] += (unsigned char)1;
            }
        } else {
            int j0 = ibase + 32 + ((rem - 1) << 6);
            if (j0 + 64 <= NPTS) {
                // Full 64-chunk: two independent streams -> 2 chains in flight.
                #pragma unroll 4
                for (int jj = 0; jj < 32; jj++) {
                    float4 p0 = pts[j0 + jj];
                    float4 p1 = pts[j0 + 32 + jj];
                    int t0 = bin_of(A, B, C, K, p0);
                    int t1 = bin_of(A, B, C, K, p1);
                    myh0[t0 << 7] += (unsigned char)1;
                    myh1[t1 << 7] += (unsigned char)1;
                }
            } else {
                // Trailing 32-chunk: split into two 16-streams.
                #pragma unroll 4
                for (int jj = 0; jj < 16; jj++) {
                    float4 p0 = pts[j0 + jj];
                    float4 p1 = pts[j0 + 16 + jj];
                    int t0 = bin_of(A, B, C, K, p0);
                    int t1 = bin_of(A, B, C, K, p1);
                    myh0[t0 << 7] += (unsigned char)1;
                    myh1[t1 << 7] += (unsigned char)1;
                }
            }
        }
    }
    __syncthreads();

    // Block reduction: warp w reduces bins {2w, 2w+1}; dp4a sums the 4 bytes
    // (both warps of the pair, both banks) of each region word.
    #pragma unroll
    for (int bb = 0; bb < 2; bb++) {
        int bin = warp * 2 + bb;
        int s = 0;
        #pragma unroll
        for (int r = 0; r < NREGIONS; r++)
            s = __dp4a((int)hist[r * 2048 + (bin << 5) + lane],
                       0x01010101, s);
        #pragma unroll
        for (int o = 16; o > 0; o >>= 1)
            s += __shfl_down_sync(0xffffffffu, s, o);
        if (lane == 0)
            g_part[blockIdx.x][bin] = s;
    }
    __threadfence();
    __syncthreads();

    __shared__ int s_last;
    if (tid == 0)
        s_last = (atomicAdd(&g_ticket, 1u) == NBLOCKS - 1);
    __syncthreads();
    if (!s_last) return;
    __threadfence();

    // --- last block: reduce 148x64 partials, cumsum, write, reset ---
    __shared__ int red[NSTEPS * 16];
    {
        int bin = tid & 63;
        int grp = tid >> 6;               // 0..15
        int s = 0;
        for (int b2 = grp; b2 < NBLOCKS; b2 += 16)
            s += g_part[b2][bin];
        red[bin * 16 + grp] = s;
    }
    __syncthreads();
    __shared__ int ecc[NSTEPS];
    if (tid < NSTEPS) {
        int tot = 0;
        #pragma unroll
        for (int g = 0; g < 16; g++) tot += red[tid * 16 + g];
        ecc[tid] = (tid == 0 ? NPTS : 0) - tot;
    }
    __syncthreads();
    if (tid < 32) {
        int e0 = ecc[tid];
        int e1 = ecc[tid + 32];
        #pragma unroll
        for (int d = 1; d < 32; d <<= 1) {
            int t = __shfl_up_sync(0xffffffffu, e0, d);
            if (tid >= d) e0 += t;
        }
        int tot = __shfl_sync(0xffffffffu, e0, 31);
        #pragma unroll
        for (int d = 1; d < 32; d <<= 1) {
            int t = __shfl_up_sync(0xffffffffu, e1, d);
            if (tid >= d) e1 += t;
        }
        e1 += tot;
        out[tid]      = (float)e0;
        out[tid + 32] = (float)e1;
    }
    if (tid == 0) g_ticket = 0;   // self-reset for graph replay
}

extern "C" void kernel_launch(void* const* d_in, const int* in_sizes, int n_in,
                              void* d_out, int out_size) {
    (void)in_sizes; (void)n_in; (void)out_size;
    const float* x = (const float*)d_in[0];
    float* out = (float*)d_out;

    cudaFuncSetAttribute(rips_ecc_kernel,
                         cudaFuncAttributeMaxDynamicSharedMemorySize, SMEM_BYTES);

    rips_ecc_kernel<<<NBLOCKS, NTHREADS, SMEM_BYTES>>>(x, out);
}